// round 4
// baseline (speedup 1.0000x reference)
#include <cuda_runtime.h>
#include <cuda_bf16.h>
#include <stdint.h>
#include <math.h>

// ---------------------------------------------------------------------------
// Scratch (__device__ globals -- no allocation allowed)
// ---------------------------------------------------------------------------
__device__ float g_offp[4][18 * 16384];        // partial offset-conv sums
__device__ float g_off[18 * 16384];            // offsets [b][18][h][w]
__device__ float g_raw[4 * 4096 * 256];        // pre-BN output, layout [b][hw][o]
__device__ float g_xT[4 * 4096 * 256];         // x transposed [b][h*w][c]
__device__ __align__(16) unsigned char g_wbf[36 * 65536]; // per-chunk swizzled Bh/Bl tiles
__device__ double g_sum[256], g_sum2[256];
__device__ float g_scale[256];
__device__ float g_shift[256];

#define SWZ(x) ((x) ^ (((x) >> 3) & 0x70))

__device__ __forceinline__ uint32_t smem_to_u32(const void* p) {
    uint32_t a;
    asm("{ .reg .u64 t; cvta.to.shared.u64 t, %1; cvt.u32.u64 %0, t; }" : "=r"(a) : "l"(p));
    return a;
}

__device__ __forceinline__ void ldsm_x4(uint32_t* r, uint32_t addr) {
    asm volatile("ldmatrix.sync.aligned.m8n8.x4.shared.b16 {%0,%1,%2,%3}, [%4];"
                 : "=r"(r[0]), "=r"(r[1]), "=r"(r[2]), "=r"(r[3]) : "r"(addr));
}

__device__ __forceinline__ void mma_bf16(float* d, const uint32_t* a, const uint32_t* b) {
    asm volatile("mma.sync.aligned.m16n8k16.row.col.f32.bf16.bf16.f32 "
                 "{%0,%1,%2,%3}, {%4,%5,%6,%7}, {%8,%9}, {%0,%1,%2,%3};"
                 : "+f"(d[0]), "+f"(d[1]), "+f"(d[2]), "+f"(d[3])
                 : "r"(a[0]), "r"(a[1]), "r"(a[2]), "r"(a[3]), "r"(b[0]), "r"(b[1]));
}

// ---------------------------------------------------------------------------
// Kernel A: transpose x [b][c][hw] -> g_xT [b][hw][c]
// ---------------------------------------------------------------------------
__global__ void k_xT(const float* __restrict__ x) {
    __shared__ float t[32][33];
    int b = blockIdx.z, c0 = blockIdx.y * 32, s0 = blockIdx.x * 32;
    int si = threadIdx.x & 31, ci = threadIdx.x >> 5;
    const float* src = x + ((size_t)b * 256 + c0) * 4096 + s0;
#pragma unroll
    for (int i = 0; i < 4; i++)
        t[ci + i * 8][si] = src[(size_t)(ci + i * 8) * 4096 + si];
    __syncthreads();
    float* dst = g_xT + (size_t)b * (4096 * 256) + (size_t)s0 * 256 + c0;
#pragma unroll
    for (int i = 0; i < 4; i++)
        dst[(size_t)(ci + i * 8) * 256 + si] = t[si][ci + i * 8];
}

// ---------------------------------------------------------------------------
// Kernel B: build swizzled bf16 hi/lo B tiles from w_def; also zero BN sums.
// chunk = k2*4+cc; row = o (256 x 128B), col = c local (64). 32KB hi + 32KB lo.
// ---------------------------------------------------------------------------
__global__ void k_prepB(const float* __restrict__ wdef) {
    int v = blockIdx.x * 256 + threadIdx.x;        // 36*256*64 = 589824
    if (v >= 589824) return;
    if (v < 256) { g_sum[v] = 0.0; g_sum2[v] = 0.0; }
    int cl = v & 63;
    int o  = (v >> 6) & 255;
    int chunk = v >> 14;
    int k2 = chunk >> 2, cc = chunk & 3;
    int c = cc * 64 + cl;
    float a = wdef[((size_t)o * 256 + c) * 9 + k2];
    __nv_bfloat16 hi = __float2bfloat16(a);
    __nv_bfloat16 lo = __float2bfloat16(a - __bfloat162float(hi));
    uint32_t byte = ((uint32_t)o << 7) + ((uint32_t)cl << 1);
    uint32_t sw = SWZ(byte);
    unsigned char* base = g_wbf + (size_t)chunk * 65536;
    *(__nv_bfloat16*)(base + sw) = hi;
    *(__nv_bfloat16*)(base + 32768 + sw) = lo;
}

// ---------------------------------------------------------------------------
// Kernel 1: offset conv (18 out ch, 3x3, pad 1), split over 4 c-chunks
// ---------------------------------------------------------------------------
__global__ void __launch_bounds__(256) k_offconv(const float* __restrict__ x,
                                                 const float* __restrict__ woff) {
    __shared__ float Wsh[18 * 64 * 9];
    int pb    = blockIdx.x & 63;
    int chunk = blockIdx.x >> 6;
    int c0    = chunk * 64;

    for (int v = threadIdx.x; v < 18 * 576; v += 256) {
        int oc = v / 576;
        int rem = v % 576;
        Wsh[v] = woff[oc * 2304 + c0 * 9 + rem];
    }
    __syncthreads();

    int pid = pb * 256 + threadIdx.x;
    int b  = pid >> 12;
    int hw = pid & 4095;
    int h = hw >> 6, w = hw & 63;

    float acc[18];
#pragma unroll
    for (int i = 0; i < 18; i++) acc[i] = 0.f;

    const float* xb = x + ((size_t)b * 256 + c0) * 4096;
    bool hv0 = (h > 0), hv2 = (h < 63), wv0 = (w > 0), wv2 = (w < 63);

    for (int cl = 0; cl < 64; cl++) {
        const float* xc = xb + (size_t)cl * 4096;
        float xr[9];
#pragma unroll
        for (int dy = 0; dy < 3; dy++) {
            int hh = h + dy - 1;
            bool hv = (dy == 0) ? hv0 : ((dy == 2) ? hv2 : true);
#pragma unroll
            for (int dx = 0; dx < 3; dx++) {
                int ww = w + dx - 1;
                bool wv = (dx == 0) ? wv0 : ((dx == 2) ? wv2 : true);
                xr[dy * 3 + dx] = (hv && wv) ? xc[hh * 64 + ww] : 0.f;
            }
        }
        const float* wp = Wsh + cl * 9;
#pragma unroll
        for (int oc = 0; oc < 18; oc++) {
            const float* wo = wp + oc * 576;
            float s = acc[oc];
#pragma unroll
            for (int t = 0; t < 9; t++) s += xr[t] * wo[t];
            acc[oc] = s;
        }
    }
#pragma unroll
    for (int oc = 0; oc < 18; oc++)
        g_offp[chunk][(b * 18 + oc) * 4096 + hw] = acc[oc];
}

__global__ void k_offcomb(const float* __restrict__ boff) {
    int v = blockIdx.x * 256 + threadIdx.x;
    if (v < 294912) {
        int oc = (v >> 12) % 18;
        g_off[v] = g_offp[0][v] + g_offp[1][v] + g_offp[2][v] + g_offp[3][v] + boff[oc];
    }
}

// ---------------------------------------------------------------------------
// Kernel 2: main GEMM on tensor cores via mma.sync (bf16 3-product split).
// CTA = 128 px (b fixed, 2 h-rows) x 128 o.  Grid 256 = 128 px-tiles x 2 n-halves.
// 8 warps: 4 (M=32px) x 2 (N=64o).  K = 36 chunks of 64 c.
// ---------------------------------------------------------------------------
#define A_HI 0
#define A_LO 16384
#define B_HI 32768
#define B_LO 49152
#define SWT_OFF 65536
#define SIX_OFF 67584
#define SMEM_TOTAL 69632

__global__ void __launch_bounds__(256, 1) k_mainMMA() {
    extern __shared__ __align__(128) char smem[];
    uint32_t sb32 = smem_to_u32(smem);
    float* sWt = (float*)(smem + SWT_OFF);   // [4][128]
    int*   sIx = (int*)(smem + SIX_OFF);     // [4][128]

    int tid = threadIdx.x, lane = tid & 31, wid = tid >> 5;
    int wm = wid & 3, wn = wid >> 2;
    int pt = blockIdx.x >> 1, nh = blockIdx.x & 1;
    int b = pt >> 5, h0 = (pt & 31) * 2;
    int n0 = nh * 128;

    float acc[2][8][4];
#pragma unroll
    for (int mt = 0; mt < 2; mt++)
#pragma unroll
        for (int j = 0; j < 8; j++)
#pragma unroll
            for (int r = 0; r < 4; r++) acc[mt][j][r] = 0.f;

    const float* xTb = g_xT + (size_t)b * (4096 * 256);

    for (int i = 0; i < 36; i++) {
        int k2 = i >> 2, cc = i & 3;

        if (cc == 0) {
            if (tid < 128) {
                int px = tid;
                int h = h0 + (px >> 6), w = px & 63;
                float offy = g_off[(b * 18 + 2 * k2)     * 4096 + h * 64 + w];
                float offx = g_off[(b * 18 + 2 * k2 + 1) * 4096 + h * 64 + w];
                float py  = offy + (float)(k2 / 3) + (float)h - 1.0f;
                float pxx = offx + (float)(k2 % 3) + (float)w - 1.0f;
                float y0f = floorf(py), x0f = floorf(pxx);
                float wy1 = py - y0f, wx1 = pxx - x0f;
                float wy0 = 1.f - wy1, wx0 = 1.f - wx1;
                bool vy0 = (y0f >= 0.f)       && (y0f <= 63.f);
                bool vy1 = (y0f + 1.f >= 0.f) && (y0f + 1.f <= 63.f);
                bool vx0 = (x0f >= 0.f)       && (x0f <= 63.f);
                bool vx1 = (x0f + 1.f >= 0.f) && (x0f + 1.f <= 63.f);
                int iy0 = min(max((int)y0f, 0), 63);
                int iy1 = min(max((int)y0f + 1, 0), 63);
                int ix0 = min(max((int)x0f, 0), 63);
                int ix1 = min(max((int)x0f + 1, 0), 63);
                sIx[0 * 128 + px] = iy0 * 64 + ix0;  sWt[0 * 128 + px] = (vy0 && vx0) ? wy0 * wx0 : 0.f;
                sIx[1 * 128 + px] = iy0 * 64 + ix1;  sWt[1 * 128 + px] = (vy0 && vx1) ? wy0 * wx1 : 0.f;
                sIx[2 * 128 + px] = iy1 * 64 + ix0;  sWt[2 * 128 + px] = (vy1 && vx0) ? wy1 * wx0 : 0.f;
                sIx[3 * 128 + px] = iy1 * 64 + ix1;  sWt[3 * 128 + px] = (vy1 && vx1) ? wy1 * wx1 : 0.f;
            }
            __syncthreads();
        }

        // copy B chunk slice (this CTA's 128 o rows): 16KB hi + 16KB lo
        {
            const float4* srch = (const float4*)(g_wbf + (size_t)i * 65536 + (size_t)n0 * 128);
            const float4* srcl = (const float4*)(g_wbf + (size_t)i * 65536 + 32768 + (size_t)n0 * 128);
            float4* dsth = (float4*)(smem + B_HI);
            float4* dstl = (float4*)(smem + B_LO);
#pragma unroll
            for (int t = 0; t < 4; t++) {
                dsth[t * 256 + tid] = srch[t * 256 + tid];
                dstl[t * 256 + tid] = srcl[t * 256 + tid];
            }
        }

        // gather A: 128 px x 64 c (bilinear, 4 corners, float4 over c) -> bf16 hi/lo
        int c0 = cc * 64;
#pragma unroll
        for (int t = 0; t < 8; t++) {
            int task = t * 256 + tid;
            int px = task >> 4;
            int cl = (task & 15) * 4;
            float w0 = sWt[0 * 128 + px], w1 = sWt[1 * 128 + px];
            float w2 = sWt[2 * 128 + px], w3 = sWt[3 * 128 + px];
            const float4 v0 = *(const float4*)(xTb + (size_t)sIx[0 * 128 + px] * 256 + c0 + cl);
            const float4 v1 = *(const float4*)(xTb + (size_t)sIx[1 * 128 + px] * 256 + c0 + cl);
            const float4 v2 = *(const float4*)(xTb + (size_t)sIx[2 * 128 + px] * 256 + c0 + cl);
            const float4 v3 = *(const float4*)(xTb + (size_t)sIx[3 * 128 + px] * 256 + c0 + cl);
            float a0 = w0 * v0.x + w1 * v1.x + w2 * v2.x + w3 * v3.x;
            float a1 = w0 * v0.y + w1 * v1.y + w2 * v2.y + w3 * v3.y;
            float a2 = w0 * v0.z + w1 * v1.z + w2 * v2.z + w3 * v3.z;
            float a3 = w0 * v0.w + w1 * v1.w + w2 * v2.w + w3 * v3.w;
            __nv_bfloat16 h0b = __float2bfloat16(a0), h1b = __float2bfloat16(a1);
            __nv_bfloat16 h2b = __float2bfloat16(a2), h3b = __float2bfloat16(a3);
            __nv_bfloat16 l0b = __float2bfloat16(a0 - __bfloat162float(h0b));
            __nv_bfloat16 l1b = __float2bfloat16(a1 - __bfloat162float(h1b));
            __nv_bfloat16 l2b = __float2bfloat16(a2 - __bfloat162float(h2b));
            __nv_bfloat16 l3b = __float2bfloat16(a3 - __bfloat162float(h3b));
            uint2 hv, lv;
            hv.x = ((uint32_t)*(uint16_t*)&h0b) | ((uint32_t)*(uint16_t*)&h1b << 16);
            hv.y = ((uint32_t)*(uint16_t*)&h2b) | ((uint32_t)*(uint16_t*)&h3b << 16);
            lv.x = ((uint32_t)*(uint16_t*)&l0b) | ((uint32_t)*(uint16_t*)&l1b << 16);
            lv.y = ((uint32_t)*(uint16_t*)&l2b) | ((uint32_t)*(uint16_t*)&l3b << 16);
            uint32_t byte = ((uint32_t)px << 7) + ((uint32_t)cl << 1);
            uint32_t sw = SWZ(byte);
            *(uint2*)(smem + A_HI + sw) = hv;
            *(uint2*)(smem + A_LO + sw) = lv;
        }

        __syncthreads();

        // MMA: 4 k16 steps, 3-product split
#pragma unroll
        for (int k16 = 0; k16 < 4; k16++) {
            uint32_t ah[2][4], al[2][4], bh[16], bl[16];
#pragma unroll
            for (int mt = 0; mt < 2; mt++) {
                int arow = wm * 32 + mt * 16 + (lane & 15);
                int acb  = k16 * 32 + ((lane >> 4) << 4);
                uint32_t off = SWZ((uint32_t)(arow * 128 + acb));
                ldsm_x4(ah[mt], sb32 + A_HI + off);
                ldsm_x4(al[mt], sb32 + A_LO + off);
            }
#pragma unroll
            for (int np = 0; np < 4; np++) {
                int brow = wn * 64 + np * 16 + ((lane >> 4) << 3) + (lane & 7);
                int bcb  = k16 * 32 + ((lane & 8) << 1);
                uint32_t off = SWZ((uint32_t)(brow * 128 + bcb));
                ldsm_x4(&bh[np * 4], sb32 + B_HI + off);
                ldsm_x4(&bl[np * 4], sb32 + B_LO + off);
            }
#pragma unroll
            for (int mt = 0; mt < 2; mt++)
#pragma unroll
                for (int j = 0; j < 8; j++) {
                    mma_bf16(acc[mt][j], ah[mt], &bh[j * 2]);
                    mma_bf16(acc[mt][j], ah[mt], &bl[j * 2]);
                    mma_bf16(acc[mt][j], al[mt], &bh[j * 2]);
                }
        }
        __syncthreads();
    }

    // epilogue: write g_raw [b][hw][o] as float2 (D frag cols are adjacent o)
    size_t rowbase = (size_t)b * 4096 + (size_t)h0 * 64;
#pragma unroll
    for (int mt = 0; mt < 2; mt++)
#pragma unroll
        for (int j = 0; j < 8; j++) {
            int px = wm * 32 + mt * 16 + (lane >> 2);
            int o  = n0 + wn * 64 + j * 8 + (lane & 3) * 2;
            float2 v01 = make_float2(acc[mt][j][0], acc[mt][j][1]);
            float2 v23 = make_float2(acc[mt][j][2], acc[mt][j][3]);
            *(float2*)(g_raw + (rowbase + px) * 256 + o)     = v01;
            *(float2*)(g_raw + (rowbase + px + 8) * 256 + o) = v23;
        }
}

// ---------------------------------------------------------------------------
// Kernel 3a: column sums over [b][hw][o] (coalesced), double atomics
// ---------------------------------------------------------------------------
__global__ void k_stats1() {
    int o = threadIdx.x;
    int r0 = blockIdx.x * 128;
    double s = 0.0, s2 = 0.0;
    for (int r = 0; r < 128; r++) {
        float v = g_raw[(size_t)(r0 + r) * 256 + o];
        s += (double)v;
        s2 += (double)v * (double)v;
    }
    atomicAdd(&g_sum[o], s);
    atomicAdd(&g_sum2[o], s2);
}

__global__ void k_stats2(const float* __restrict__ gamma, const float* __restrict__ beta) {
    int o = threadIdx.x;
    double mean = g_sum[o] / 16384.0;
    double var  = g_sum2[o] / 16384.0 - mean * mean;
    float scale = gamma[o] * rsqrtf((float)var + 1e-5f);
    g_scale[o] = scale;
    g_shift[o] = beta[o] - (float)mean * scale;
}

// ---------------------------------------------------------------------------
// Kernel 4: normalize + ReLU + transpose [b][hw][o] -> out [b][o][hw]
// grid: (512 row-tiles, 8 o-tiles), 256 threads, 32x32 tiles
// ---------------------------------------------------------------------------
__global__ void k_normT(float* __restrict__ out) {
    __shared__ float t[32][33];
    int r0 = blockIdx.x * 32;          // global row (b*4096 + hw)
    int o0 = blockIdx.y * 32;
    int si = threadIdx.x & 31, ri = threadIdx.x >> 5;
#pragma unroll
    for (int i = 0; i < 4; i++)
        t[ri + i * 8][si] = g_raw[(size_t)(r0 + ri + i * 8) * 256 + o0 + si];
    __syncthreads();
    int bq = r0 >> 12;
    int hw0 = r0 & 4095;
#pragma unroll
    for (int i = 0; i < 4; i++) {
        int o = o0 + ri + i * 8;
        float sc = g_scale[o], sh = g_shift[o];
        float v = t[si][ri + i * 8];
        out[((size_t)bq * 256 + o) * 4096 + hw0 + si] = fmaxf(v * sc + sh, 0.f);
    }
}

// ---------------------------------------------------------------------------
extern "C" void kernel_launch(void* const* d_in, const int* in_sizes, int n_in,
                              void* d_out, int out_size) {
    const float* x     = (const float*)d_in[0];
    const float* woff  = (const float*)d_in[1];
    const float* boff  = (const float*)d_in[2];
    const float* wdef  = (const float*)d_in[3];
    const float* gamma = (const float*)d_in[4];
    const float* beta  = (const float*)d_in[5];
    float* out = (float*)d_out;

    cudaFuncSetAttribute(k_mainMMA, cudaFuncAttributeMaxDynamicSharedMemorySize, SMEM_TOTAL);

    k_xT<<<dim3(128, 8, 4), 256>>>(x);
    k_prepB<<<2304, 256>>>(wdef);
    k_offconv<<<256, 256>>>(x, woff);
    k_offcomb<<<1152, 256>>>(boff);
    k_mainMMA<<<256, 256, SMEM_TOTAL>>>();
    k_stats1<<<128, 256>>>();
    k_stats2<<<1, 256>>>(gamma, beta);
    k_normT<<<dim3(512, 8), 256>>>(out);
}

// round 5
// speedup vs baseline: 1.9864x; 1.9864x over previous
#include <cuda_runtime.h>
#include <cuda_bf16.h>
#include <stdint.h>
#include <math.h>

// ---------------------------------------------------------------------------
// Scratch (__device__ globals -- no allocation allowed)
// ---------------------------------------------------------------------------
__device__ float g_offp[4][18 * 16384];        // partial offset-conv sums
__device__ float g_off[18 * 16384];            // offsets [b][18][h][w]
__device__ float g_raw[4 * 4096 * 256];        // pre-BN output, layout [b][hw][o]
__device__ float g_xT[4 * 4096 * 256];         // x transposed [b][h*w][c]
__device__ __align__(16) unsigned char g_wbf[36 * 65536]; // per-chunk swizzled Bh/Bl tiles
__device__ double g_sum[256], g_sum2[256];
__device__ float g_scale[256];
__device__ float g_shift[256];

#define SWZ(x) ((x) ^ (((x) >> 3) & 0x70))

__device__ __forceinline__ uint32_t smem_to_u32(const void* p) {
    uint32_t a;
    asm("{ .reg .u64 t; cvta.to.shared.u64 t, %1; cvt.u32.u64 %0, t; }" : "=r"(a) : "l"(p));
    return a;
}

__device__ __forceinline__ void ldsm_x4(uint32_t* r, uint32_t addr) {
    asm volatile("ldmatrix.sync.aligned.m8n8.x4.shared.b16 {%0,%1,%2,%3}, [%4];"
                 : "=r"(r[0]), "=r"(r[1]), "=r"(r[2]), "=r"(r[3]) : "r"(addr));
}

__device__ __forceinline__ void mma_bf16(float* d, const uint32_t* a, const uint32_t* b) {
    asm volatile("mma.sync.aligned.m16n8k16.row.col.f32.bf16.bf16.f32 "
                 "{%0,%1,%2,%3}, {%4,%5,%6,%7}, {%8,%9}, {%0,%1,%2,%3};"
                 : "+f"(d[0]), "+f"(d[1]), "+f"(d[2]), "+f"(d[3])
                 : "r"(a[0]), "r"(a[1]), "r"(a[2]), "r"(a[3]), "r"(b[0]), "r"(b[1]));
}

__device__ __forceinline__ void cp_async16(uint32_t smem_addr, const void* gmem) {
    asm volatile("cp.async.cg.shared.global [%0], [%1], 16;"
                 :: "r"(smem_addr), "l"(gmem));
}
#define CP_COMMIT() asm volatile("cp.async.commit_group;" ::: "memory")
#define CP_WAIT0()  asm volatile("cp.async.wait_group 0;" ::: "memory")

// ---------------------------------------------------------------------------
// Kernel 0 (merged prep): blocks [0,4096) transpose x -> g_xT [b][hw][c];
// blocks [4096,6400) build swizzled bf16 hi/lo B tiles + zero BN sums.
// ---------------------------------------------------------------------------
__global__ void k_prep(const float* __restrict__ x, const float* __restrict__ wdef) {
    __shared__ float t[32][33];
    if (blockIdx.x < 4096) {
        int bid = blockIdx.x;
        int b = bid >> 10, c0 = ((bid >> 7) & 7) * 32, s0 = (bid & 127) * 32;
        int si = threadIdx.x & 31, ci = threadIdx.x >> 5;
        const float* src = x + ((size_t)b * 256 + c0) * 4096 + s0;
#pragma unroll
        for (int i = 0; i < 4; i++)
            t[ci + i * 8][si] = src[(size_t)(ci + i * 8) * 4096 + si];
        __syncthreads();
        float* dst = g_xT + (size_t)b * (4096 * 256) + (size_t)s0 * 256 + c0;
#pragma unroll
        for (int i = 0; i < 4; i++)
            dst[(size_t)(ci + i * 8) * 256 + si] = t[si][ci + i * 8];
    } else {
        int v = (blockIdx.x - 4096) * 256 + threadIdx.x;   // 2304*256 = 589824
        if (v < 256) { g_sum[v] = 0.0; g_sum2[v] = 0.0; }
        int cl = v & 63;
        int o  = (v >> 6) & 255;
        int chunk = v >> 14;
        int k2 = chunk >> 2, cc = chunk & 3;
        int c = cc * 64 + cl;
        float a = wdef[((size_t)o * 256 + c) * 9 + k2];
        __nv_bfloat16 hi = __float2bfloat16(a);
        __nv_bfloat16 lo = __float2bfloat16(a - __bfloat162float(hi));
        uint32_t byte = ((uint32_t)o << 7) + ((uint32_t)cl << 1);
        uint32_t sw = SWZ(byte);
        unsigned char* base = g_wbf + (size_t)chunk * 65536;
        *(__nv_bfloat16*)(base + sw) = hi;
        *(__nv_bfloat16*)(base + 32768 + sw) = lo;
    }
}

// ---------------------------------------------------------------------------
// Kernel 1: offset conv (18 out ch, 3x3, pad 1), split over 4 c-chunks
// ---------------------------------------------------------------------------
__global__ void __launch_bounds__(256) k_offconv(const float* __restrict__ x,
                                                 const float* __restrict__ woff) {
    __shared__ float Wsh[18 * 64 * 9];
    int pb    = blockIdx.x & 63;
    int chunk = blockIdx.x >> 6;
    int c0    = chunk * 64;

    for (int v = threadIdx.x; v < 18 * 576; v += 256) {
        int oc = v / 576;
        int rem = v % 576;
        Wsh[v] = woff[oc * 2304 + c0 * 9 + rem];
    }
    __syncthreads();

    int pid = pb * 256 + threadIdx.x;
    int b  = pid >> 12;
    int hw = pid & 4095;
    int h = hw >> 6, w = hw & 63;

    float acc[18];
#pragma unroll
    for (int i = 0; i < 18; i++) acc[i] = 0.f;

    const float* xb = x + ((size_t)b * 256 + c0) * 4096;
    bool hv0 = (h > 0), hv2 = (h < 63), wv0 = (w > 0), wv2 = (w < 63);

    for (int cl = 0; cl < 64; cl++) {
        const float* xc = xb + (size_t)cl * 4096;
        float xr[9];
#pragma unroll
        for (int dy = 0; dy < 3; dy++) {
            int hh = h + dy - 1;
            bool hv = (dy == 0) ? hv0 : ((dy == 2) ? hv2 : true);
#pragma unroll
            for (int dx = 0; dx < 3; dx++) {
                int ww = w + dx - 1;
                bool wv = (dx == 0) ? wv0 : ((dx == 2) ? wv2 : true);
                xr[dy * 3 + dx] = (hv && wv) ? xc[hh * 64 + ww] : 0.f;
            }
        }
        const float* wp = Wsh + cl * 9;
#pragma unroll
        for (int oc = 0; oc < 18; oc++) {
            const float* wo = wp + oc * 576;
            float s = acc[oc];
#pragma unroll
            for (int t = 0; t < 9; t++) s += xr[t] * wo[t];
            acc[oc] = s;
        }
    }
#pragma unroll
    for (int oc = 0; oc < 18; oc++)
        g_offp[chunk][(b * 18 + oc) * 4096 + hw] = acc[oc];
}

__global__ void k_offcomb(const float* __restrict__ boff) {
    int v = blockIdx.x * 256 + threadIdx.x;
    if (v < 294912) {
        int oc = (v >> 12) % 18;
        g_off[v] = g_offp[0][v] + g_offp[1][v] + g_offp[2][v] + g_offp[3][v] + boff[oc];
    }
}

// ---------------------------------------------------------------------------
// Kernel 2: main GEMM on tensor cores via mma.sync (bf16 3-product split).
// CTA = 128 px (b fixed, 2 h-rows) x 128 o.  Grid 256 = 128 px-tiles x 2 n-halves.
// 8 warps: 4 (M=32px) x 2 (N=64o).  K = 36 chunks of 64 c.
// occupancy 2 CTAs/SM: cross-CTA overlap of gather (LSU/FMA) and MMA (tensor).
// B tile arrives by cp.async, hidden under gather.
// ---------------------------------------------------------------------------
#define A_HI 0
#define A_LO 16384
#define B_HI 32768
#define B_LO 49152
#define SWT_OFF 65536
#define SIX_OFF 67584
#define SMEM_TOTAL 69632

__global__ void __launch_bounds__(256, 2) k_mainMMA() {
    extern __shared__ __align__(128) char smem[];
    uint32_t sb32 = smem_to_u32(smem);
    float* sWt = (float*)(smem + SWT_OFF);   // [4][128]
    int*   sIx = (int*)(smem + SIX_OFF);     // [4][128]

    int tid = threadIdx.x, lane = tid & 31, wid = tid >> 5;
    int wm = wid & 3, wn = wid >> 2;
    int pt = blockIdx.x >> 1, nh = blockIdx.x & 1;
    int b = pt >> 5, h0 = (pt & 31) * 2;
    int n0 = nh * 128;

    float acc[2][8][4];
#pragma unroll
    for (int mt = 0; mt < 2; mt++)
#pragma unroll
        for (int j = 0; j < 8; j++)
#pragma unroll
            for (int r = 0; r < 4; r++) acc[mt][j][r] = 0.f;

    const float* xTb = g_xT + (size_t)b * (4096 * 256);

    for (int i = 0; i < 36; i++) {
        int k2 = i >> 2, cc = i & 3;

        // B tile for this chunk via cp.async (prev MMA done: sync at loop end)
        {
            const char* srch = (const char*)g_wbf + (size_t)i * 65536 + (size_t)n0 * 128;
            const char* srcl = srch + 32768;
#pragma unroll
            for (int t = 0; t < 4; t++) {
                uint32_t off = (uint32_t)(t * 256 + tid) * 16;
                cp_async16(sb32 + B_HI + off, srch + off);
                cp_async16(sb32 + B_LO + off, srcl + off);
            }
            CP_COMMIT();
        }

        if (cc == 0) {
            if (tid < 128) {
                int px = tid;
                int h = h0 + (px >> 6), w = px & 63;
                float offy = g_off[(b * 18 + 2 * k2)     * 4096 + h * 64 + w];
                float offx = g_off[(b * 18 + 2 * k2 + 1) * 4096 + h * 64 + w];
                float py  = offy + (float)(k2 / 3) + (float)h - 1.0f;
                float pxx = offx + (float)(k2 % 3) + (float)w - 1.0f;
                float y0f = floorf(py), x0f = floorf(pxx);
                float wy1 = py - y0f, wx1 = pxx - x0f;
                float wy0 = 1.f - wy1, wx0 = 1.f - wx1;
                bool vy0 = (y0f >= 0.f)       && (y0f <= 63.f);
                bool vy1 = (y0f + 1.f >= 0.f) && (y0f + 1.f <= 63.f);
                bool vx0 = (x0f >= 0.f)       && (x0f <= 63.f);
                bool vx1 = (x0f + 1.f >= 0.f) && (x0f + 1.f <= 63.f);
                int iy0 = min(max((int)y0f, 0), 63);
                int iy1 = min(max((int)y0f + 1, 0), 63);
                int ix0 = min(max((int)x0f, 0), 63);
                int ix1 = min(max((int)x0f + 1, 0), 63);
                sIx[0 * 128 + px] = iy0 * 64 + ix0;  sWt[0 * 128 + px] = (vy0 && vx0) ? wy0 * wx0 : 0.f;
                sIx[1 * 128 + px] = iy0 * 64 + ix1;  sWt[1 * 128 + px] = (vy0 && vx1) ? wy0 * wx1 : 0.f;
                sIx[2 * 128 + px] = iy1 * 64 + ix0;  sWt[2 * 128 + px] = (vy1 && vx0) ? wy1 * wx0 : 0.f;
                sIx[3 * 128 + px] = iy1 * 64 + ix1;  sWt[3 * 128 + px] = (vy1 && vx1) ? wy1 * wx1 : 0.f;
            }
            __syncthreads();
        }

        // gather A: 128 px x 64 c (bilinear, 4 corners, float4 over c) -> bf16 hi/lo
        int c0 = cc * 64;
#pragma unroll
        for (int t = 0; t < 8; t++) {
            int task = t * 256 + tid;
            int px = task >> 4;
            int cl = (task & 15) * 4;
            float w0 = sWt[0 * 128 + px], w1 = sWt[1 * 128 + px];
            float w2 = sWt[2 * 128 + px], w3 = sWt[3 * 128 + px];
            const float4 v0 = *(const float4*)(xTb + (size_t)sIx[0 * 128 + px] * 256 + c0 + cl);
            const float4 v1 = *(const float4*)(xTb + (size_t)sIx[1 * 128 + px] * 256 + c0 + cl);
            const float4 v2 = *(const float4*)(xTb + (size_t)sIx[2 * 128 + px] * 256 + c0 + cl);
            const float4 v3 = *(const float4*)(xTb + (size_t)sIx[3 * 128 + px] * 256 + c0 + cl);
            float a0 = w0 * v0.x + w1 * v1.x + w2 * v2.x + w3 * v3.x;
            float a1 = w0 * v0.y + w1 * v1.y + w2 * v2.y + w3 * v3.y;
            float a2 = w0 * v0.z + w1 * v1.z + w2 * v2.z + w3 * v3.z;
            float a3 = w0 * v0.w + w1 * v1.w + w2 * v2.w + w3 * v3.w;
            __nv_bfloat16 h0b = __float2bfloat16(a0), h1b = __float2bfloat16(a1);
            __nv_bfloat16 h2b = __float2bfloat16(a2), h3b = __float2bfloat16(a3);
            __nv_bfloat16 l0b = __float2bfloat16(a0 - __bfloat162float(h0b));
            __nv_bfloat16 l1b = __float2bfloat16(a1 - __bfloat162float(h1b));
            __nv_bfloat16 l2b = __float2bfloat16(a2 - __bfloat162float(h2b));
            __nv_bfloat16 l3b = __float2bfloat16(a3 - __bfloat162float(h3b));
            uint2 hv, lv;
            hv.x = ((uint32_t)*(uint16_t*)&h0b) | ((uint32_t)*(uint16_t*)&h1b << 16);
            hv.y = ((uint32_t)*(uint16_t*)&h2b) | ((uint32_t)*(uint16_t*)&h3b << 16);
            lv.x = ((uint32_t)*(uint16_t*)&l0b) | ((uint32_t)*(uint16_t*)&l1b << 16);
            lv.y = ((uint32_t)*(uint16_t*)&l2b) | ((uint32_t)*(uint16_t*)&l3b << 16);
            uint32_t byte = ((uint32_t)px << 7) + ((uint32_t)cl << 1);
            uint32_t sw = SWZ(byte);
            *(uint2*)(smem + A_HI + sw) = hv;
            *(uint2*)(smem + A_LO + sw) = lv;
        }

        CP_WAIT0();
        __syncthreads();

        // MMA: 4 k16 steps, 3-product split; B frags loaded per n16 slice
#pragma unroll
        for (int k16 = 0; k16 < 4; k16++) {
            uint32_t ah[2][4], al[2][4];
#pragma unroll
            for (int mt = 0; mt < 2; mt++) {
                int arow = wm * 32 + mt * 16 + (lane & 15);
                int acb  = k16 * 32 + ((lane >> 4) << 4);
                uint32_t off = SWZ((uint32_t)(arow * 128 + acb));
                ldsm_x4(ah[mt], sb32 + A_HI + off);
                ldsm_x4(al[mt], sb32 + A_LO + off);
            }
#pragma unroll
            for (int np = 0; np < 4; np++) {
                uint32_t bh[4], bl[4];
                int brow = wn * 64 + np * 16 + ((lane >> 4) << 3) + (lane & 7);
                int bcb  = k16 * 32 + ((lane & 8) << 1);
                uint32_t off = SWZ((uint32_t)(brow * 128 + bcb));
                ldsm_x4(bh, sb32 + B_HI + off);
                ldsm_x4(bl, sb32 + B_LO + off);
#pragma unroll
                for (int mt = 0; mt < 2; mt++)
#pragma unroll
                    for (int jj = 0; jj < 2; jj++) {
                        int j = np * 2 + jj;
                        mma_bf16(acc[mt][j], ah[mt], &bh[jj * 2]);
                        mma_bf16(acc[mt][j], ah[mt], &bl[jj * 2]);
                        mma_bf16(acc[mt][j], al[mt], &bh[jj * 2]);
                    }
            }
        }
        __syncthreads();
    }

    // epilogue: write g_raw [b][hw][o] as float2 (D frag cols are adjacent o)
    size_t rowbase = (size_t)b * 4096 + (size_t)h0 * 64;
#pragma unroll
    for (int mt = 0; mt < 2; mt++)
#pragma unroll
        for (int j = 0; j < 8; j++) {
            int px = wm * 32 + mt * 16 + (lane >> 2);
            int o  = n0 + wn * 64 + j * 8 + (lane & 3) * 2;
            float2 v01 = make_float2(acc[mt][j][0], acc[mt][j][1]);
            float2 v23 = make_float2(acc[mt][j][2], acc[mt][j][3]);
            *(float2*)(g_raw + (rowbase + px) * 256 + o)     = v01;
            *(float2*)(g_raw + (rowbase + px + 8) * 256 + o) = v23;
        }
}

// ---------------------------------------------------------------------------
// Kernel 3a: column sums over [b][hw][o] (coalesced), double atomics
// ---------------------------------------------------------------------------
__global__ void k_stats1() {
    int o = threadIdx.x;
    int r0 = blockIdx.x * 128;
    double s = 0.0, s2 = 0.0;
    for (int r = 0; r < 128; r++) {
        float v = g_raw[(size_t)(r0 + r) * 256 + o];
        s += (double)v;
        s2 += (double)v * (double)v;
    }
    atomicAdd(&g_sum[o], s);
    atomicAdd(&g_sum2[o], s2);
}

__global__ void k_stats2(const float* __restrict__ gamma, const float* __restrict__ beta) {
    int o = threadIdx.x;
    double mean = g_sum[o] / 16384.0;
    double var  = g_sum2[o] / 16384.0 - mean * mean;
    float scale = gamma[o] * rsqrtf((float)var + 1e-5f);
    g_scale[o] = scale;
    g_shift[o] = beta[o] - (float)mean * scale;
}

// ---------------------------------------------------------------------------
// Kernel 4: normalize + ReLU + transpose [b][hw][o] -> out [b][o][hw]
// ---------------------------------------------------------------------------
__global__ void k_normT(float* __restrict__ out) {
    __shared__ float t[32][33];
    int r0 = blockIdx.x * 32;          // global row (b*4096 + hw)
    int o0 = blockIdx.y * 32;
    int si = threadIdx.x & 31, ri = threadIdx.x >> 5;
#pragma unroll
    for (int i = 0; i < 4; i++)
        t[ri + i * 8][si] = g_raw[(size_t)(r0 + ri + i * 8) * 256 + o0 + si];
    __syncthreads();
    int bq = r0 >> 12;
    int hw0 = r0 & 4095;
#pragma unroll
    for (int i = 0; i < 4; i++) {
        int o = o0 + ri + i * 8;
        float sc = g_scale[o], sh = g_shift[o];
        float v = t[si][ri + i * 8];
        out[((size_t)bq * 256 + o) * 4096 + hw0 + si] = fmaxf(v * sc + sh, 0.f);
    }
}

// ---------------------------------------------------------------------------
extern "C" void kernel_launch(void* const* d_in, const int* in_sizes, int n_in,
                              void* d_out, int out_size) {
    const float* x     = (const float*)d_in[0];
    const float* woff  = (const float*)d_in[1];
    const float* boff  = (const float*)d_in[2];
    const float* wdef  = (const float*)d_in[3];
    const float* gamma = (const float*)d_in[4];
    const float* beta  = (const float*)d_in[5];
    float* out = (float*)d_out;

    cudaFuncSetAttribute(k_mainMMA, cudaFuncAttributeMaxDynamicSharedMemorySize, SMEM_TOTAL);

    k_prep<<<6400, 256>>>(x, wdef);
    k_offconv<<<256, 256>>>(x, woff);
    k_offcomb<<<1152, 256>>>(boff);
    k_mainMMA<<<256, 256, SMEM_TOTAL>>>();   // launch index 3 -> ncu capture slot
    k_stats1<<<128, 256>>>();
    k_stats2<<<1, 256>>>(gamma, beta);
    k_normT<<<dim3(512, 8), 256>>>(out);
}